// round 1
// baseline (speedup 1.0000x reference)
#include <cuda_runtime.h>

// FixedGaussianBlur: depthwise 21x21 Gaussian (sigma=3), reflect padding,
// x[32,3,512,512] f32 -> y[32,3,512,512] f32.
// Separable + fused: one kernel, horizontal pass into smem, vertical pass in
// registers. Weights are compile-time literals so ptxas emits FFMA-imm (rt=1).

#define IMG_W 512
#define IMG_H 512
#define PAD 10
#define KS 21
#define TW 64
#define TH 32
#define SIN_W (TW + 2 * PAD)   // 84
#define SIN_H (TH + 2 * PAD)   // 52
#define NTHREADS 256
#define NIMG 96                // 32 * 3 depthwise planes

// 1D normalized Gaussian taps, w[j] = exp(-(j-10)^2/18) / sum  (sigma = 3)
__device__ __constant__ const float WT_c[KS] = {0};  // unused; keep literals below
#define W0  0.13303900f
#define W1  0.12584950f
#define W2  0.10652928f
#define W3  0.08069223f
#define W4  0.05469397f
#define W5  0.03317359f
#define W6  0.01800488f
#define W7  0.00874446f
#define W8  0.00380033f
#define W9  0.00147793f
#define W10 0.00051432f

__device__ __forceinline__ float tap(int j) {
    // compile-time resolved under full unroll
    constexpr float w[KS] = {W10, W9, W8, W7, W6, W5, W4, W3, W2, W1, W0,
                             W1, W2, W3, W4, W5, W6, W7, W8, W9, W10};
    return w[j];
}

__device__ __forceinline__ int reflect_idx(int i, int n) {
    i = (i < 0) ? -i : i;
    i = (i >= n) ? (2 * n - 2 - i) : i;
    return i;
}

__global__ __launch_bounds__(NTHREADS)
void gauss_blur_fused(const float* __restrict__ in, float* __restrict__ out) {
    __shared__ __align__(16) float s_in[SIN_H][SIN_W];  // 52*84*4 = 17472 B
    __shared__ __align__(16) float s_h[SIN_H][TW];      // 52*64*4 = 13312 B

    const int tid = threadIdx.x;
    const int x0 = blockIdx.x * TW;
    const int y0 = blockIdx.y * TH;
    const float* __restrict__ base = in + (size_t)blockIdx.z * (IMG_W * IMG_H);

    // ---- Load input tile (with halo) into smem ----
    const bool interior = (x0 >= PAD) && (x0 + TW + PAD <= IMG_W) &&
                          (y0 >= PAD) && (y0 + TH + PAD <= IMG_H);
    {
        int r = tid / SIN_W;
        int c = tid - r * SIN_W;
        if (interior) {
            const float* src = base + (size_t)(y0 - PAD) * IMG_W + (x0 - PAD);
            #pragma unroll
            for (int it = 0; it < (SIN_H * SIN_W + NTHREADS - 1) / NTHREADS; ++it) {
                int idx = tid + it * NTHREADS;
                if (idx < SIN_H * SIN_W) {
                    s_in[r][c] = __ldg(src + r * IMG_W + c);
                }
                // advance (r,c) by 256 = 3*84 + 4
                c += 4; r += 3;
                if (c >= SIN_W) { c -= SIN_W; r += 1; }
            }
        } else {
            #pragma unroll
            for (int it = 0; it < (SIN_H * SIN_W + NTHREADS - 1) / NTHREADS; ++it) {
                int idx = tid + it * NTHREADS;
                if (idx < SIN_H * SIN_W) {
                    int gy = reflect_idx(y0 - PAD + r, IMG_H);
                    int gx = reflect_idx(x0 - PAD + c, IMG_W);
                    s_in[r][c] = __ldg(base + (size_t)gy * IMG_W + gx);
                }
                c += 4; r += 3;
                if (c >= SIN_W) { c -= SIN_W; r += 1; }
            }
        }
    }
    __syncthreads();

    // ---- Horizontal pass: 52 rows x 4 segments of 16 outputs ----
    if (tid < SIN_H * 4) {
        const int row = tid >> 2;
        const int seg = (tid & 3) * 16;
        float v[36];
        const float4* p = reinterpret_cast<const float4*>(&s_in[row][seg]);
        #pragma unroll
        for (int q = 0; q < 9; ++q) {
            float4 t = p[q];
            v[4 * q + 0] = t.x; v[4 * q + 1] = t.y;
            v[4 * q + 2] = t.z; v[4 * q + 3] = t.w;
        }
        #pragma unroll
        for (int c = 0; c < 16; ++c) {
            float acc = v[c] * tap(0);
            #pragma unroll
            for (int j = 1; j < KS; ++j) acc = fmaf(v[c + j], tap(j), acc);
            s_h[row][seg + c] = acc;
        }
    }
    __syncthreads();

    // ---- Vertical pass: each thread owns one column, 8 outputs ----
    const int col = tid & (TW - 1);
    const int yg = (tid >> 6) * 8;   // 4 groups of 8 rows

    float acc[8];
    #pragma unroll
    for (int o = 0; o < 8; ++o) acc[o] = 0.0f;

    #pragma unroll
    for (int t = 0; t < 28; ++t) {
        float v = s_h[yg + t][col];
        #pragma unroll
        for (int o = 0; o < 8; ++o) {
            int j = t - o;
            if (j >= 0 && j < KS) acc[o] = fmaf(v, tap(j), acc[o]);
        }
    }

    float* dst = out + (size_t)blockIdx.z * (IMG_W * IMG_H)
                     + (size_t)(y0 + yg) * IMG_W + (x0 + col);
    #pragma unroll
    for (int o = 0; o < 8; ++o) dst[(size_t)o * IMG_W] = acc[o];
}

extern "C" void kernel_launch(void* const* d_in, const int* in_sizes, int n_in,
                              void* d_out, int out_size) {
    (void)in_sizes; (void)n_in; (void)out_size;
    const float* x = (const float*)d_in[0];
    float* y = (float*)d_out;
    dim3 grid(IMG_W / TW, IMG_H / TH, NIMG);  // 8 x 16 x 96
    gauss_blur_fused<<<grid, NTHREADS>>>(x, y);
}

// round 2
// speedup vs baseline: 1.1542x; 1.1542x over previous
#include <cuda_runtime.h>

// FixedGaussianBlur: depthwise 21x21 Gaussian (sigma=3), reflect padding,
// x[32,3,512,512] f32 -> y[32,3,512,512] f32.
// Separable, fused, single smem tile with IN-PLACE horizontal pass.
// Tile 64x64 outputs, halo 10 -> 84x84 smem tile (28.2 KB), 512 threads.

#define IMG_W 512
#define IMG_H 512
#define PAD 10
#define KS 21
#define TW 64
#define TH 64
#define SIN_W 84
#define SIN_H 84
#define NTHREADS 512
#define NIMG 96                // 32 * 3 depthwise planes
#define NLOAD (SIN_W * SIN_H)  // 7056

// 1D normalized Gaussian taps (sigma = 3), compile-time literals -> FFMA-imm
#define W0  0.13303900f
#define W1  0.12584950f
#define W2  0.10652928f
#define W3  0.08069223f
#define W4  0.05469397f
#define W5  0.03317359f
#define W6  0.01800488f
#define W7  0.00874446f
#define W8  0.00380033f
#define W9  0.00147793f
#define W10 0.00051432f

__device__ __forceinline__ float tap(int j) {
    constexpr float w[KS] = {W10, W9, W8, W7, W6, W5, W4, W3, W2, W1, W0,
                             W1, W2, W3, W4, W5, W6, W7, W8, W9, W10};
    return w[j];
}

__device__ __forceinline__ int reflect_idx(int i, int n) {
    i = (i < 0) ? -i : i;
    i = (i >= n) ? (2 * n - 2 - i) : i;
    return i;
}

__global__ __launch_bounds__(NTHREADS)
void gauss_blur_fused(const float* __restrict__ in, float* __restrict__ out) {
    __shared__ __align__(16) float s[SIN_H][SIN_W];  // 84*84*4 = 28224 B

    const int tid = threadIdx.x;
    const int x0 = blockIdx.x * TW;
    const int y0 = blockIdx.y * TH;
    const float* __restrict__ base = in + (size_t)blockIdx.z * (IMG_W * IMG_H);

    // ---- Load 84x84 input tile (with halo) ----
    const bool interior = (x0 >= PAD) && (x0 + TW + PAD <= IMG_W) &&
                          (y0 >= PAD) && (y0 + TH + PAD <= IMG_H);
    {
        int r = tid / SIN_W;
        int c = tid - r * SIN_W;
        float* sflat = &s[0][0];
        if (interior) {
            const float* g = base + (size_t)(y0 - PAD + r) * IMG_W + (x0 - PAD + c);
            int sidx = r * SIN_W + c;
            #pragma unroll
            for (int it = 0; it < (NLOAD + NTHREADS - 1) / NTHREADS; ++it) {
                if (r < SIN_H) sflat[sidx] = __ldg(g);
                // advance by 512 elements: r += 6, c += 8 (512 = 6*84 + 8)
                c += 8;
                bool wrap = (c >= SIN_W);
                c = wrap ? (c - SIN_W) : c;
                r += wrap ? 7 : 6;
                g += wrap ? (7 * IMG_W + 8 - SIN_W) : (6 * IMG_W + 8);
                sidx += NTHREADS;
            }
        } else {
            #pragma unroll
            for (int it = 0; it < (NLOAD + NTHREADS - 1) / NTHREADS; ++it) {
                if (r < SIN_H) {
                    int gy = reflect_idx(y0 - PAD + r, IMG_H);
                    int gx = reflect_idx(x0 - PAD + c, IMG_W);
                    sflat[r * SIN_W + c] = __ldg(base + (size_t)gy * IMG_W + gx);
                }
                c += 8;
                bool wrap = (c >= SIN_W);
                c = wrap ? (c - SIN_W) : c;
                r += wrap ? 7 : 6;
            }
        }
    }
    __syncthreads();

    // ---- Horizontal pass, IN PLACE: 84 rows x 4 segments of 16 outputs ----
    // Read window into registers, sync, write filtered values over cols 0..63.
    {
        const bool hactive = (tid < SIN_H * 4);  // 336 of 512
        const int row = tid >> 2;
        const int seg = (tid & 3) << 4;
        float v[36];
        float o[16];
        if (hactive) {
            const float4* p = reinterpret_cast<const float4*>(&s[row][seg]);
            #pragma unroll
            for (int q = 0; q < 9; ++q) {
                float4 t = p[q];
                v[4 * q + 0] = t.x; v[4 * q + 1] = t.y;
                v[4 * q + 2] = t.z; v[4 * q + 3] = t.w;
            }
            #pragma unroll
            for (int c = 0; c < 16; ++c) {
                float acc = v[c] * tap(0);
                #pragma unroll
                for (int j = 1; j < KS; ++j) acc = fmaf(v[c + j], tap(j), acc);
                o[c] = acc;
            }
        }
        __syncthreads();   // all reads of raw tile complete
        if (hactive) {
            float4* q = reinterpret_cast<float4*>(&s[row][seg]);
            #pragma unroll
            for (int k = 0; k < 4; ++k)
                q[k] = make_float4(o[4 * k], o[4 * k + 1], o[4 * k + 2], o[4 * k + 3]);
        }
    }
    __syncthreads();

    // ---- Vertical pass: each thread owns one column, 8 consecutive rows ----
    const int col = tid & (TW - 1);
    const int g8 = (tid >> 6) << 3;   // 0,8,...,56

    float acc[8];
    #pragma unroll
    for (int o = 0; o < 8; ++o) acc[o] = 0.0f;

    #pragma unroll
    for (int t = 0; t < 28; ++t) {
        float v = s[g8 + t][col];
        #pragma unroll
        for (int o = 0; o < 8; ++o) {
            int j = t - o;
            if (j >= 0 && j < KS) acc[o] = fmaf(v, tap(j), acc[o]);
        }
    }

    float* dst = out + (size_t)blockIdx.z * (IMG_W * IMG_H)
                     + (size_t)(y0 + g8) * IMG_W + (x0 + col);
    #pragma unroll
    for (int o = 0; o < 8; ++o) dst[(size_t)o * IMG_W] = acc[o];
}

extern "C" void kernel_launch(void* const* d_in, const int* in_sizes, int n_in,
                              void* d_out, int out_size) {
    (void)in_sizes; (void)n_in; (void)out_size;
    const float* x = (const float*)d_in[0];
    float* y = (float*)d_out;
    dim3 grid(IMG_W / TW, IMG_H / TH, NIMG);  // 8 x 8 x 96
    gauss_blur_fused<<<grid, NTHREADS>>>(x, y);
}

// round 3
// speedup vs baseline: 1.2422x; 1.0763x over previous
#include <cuda_runtime.h>
#include <cstdint>

// FixedGaussianBlur: depthwise 21x21 Gaussian (sigma=3), reflect padding,
// x[32,3,512,512] f32 -> y[32,3,512,512] f32.
// Separable, fused. 64x64 tile, halo 10 -> 84x84 smem (28.2 KB), 512 threads.
// Horizontal pass scalar in-place; vertical pass packed f32x2 (FFMA2) over
// column pairs (adjacent cols are contiguous in smem -> free packed operands).

#define IMG_W 512
#define IMG_H 512
#define PAD 10
#define KS 21
#define TW 64
#define TH 64
#define SIN_W 84
#define SIN_H 84
#define NTHREADS 512
#define NIMG 96
#define NLOAD (SIN_W * SIN_H)      // 7056
#define NLOAD2 (NLOAD / 2)         // 3528 float2

#define W0  0.13303900f
#define W1  0.12584950f
#define W2  0.10652928f
#define W3  0.08069223f
#define W4  0.05469397f
#define W5  0.03317359f
#define W6  0.01800488f
#define W7  0.00874446f
#define W8  0.00380033f
#define W9  0.00147793f
#define W10 0.00051432f

__device__ __forceinline__ float tap(int j) {
    constexpr float w[KS] = {W10, W9, W8, W7, W6, W5, W4, W3, W2, W1, W0,
                             W1, W2, W3, W4, W5, W6, W7, W8, W9, W10};
    return w[j];
}

__device__ __forceinline__ int reflect_idx(int i, int n) {
    i = (i < 0) ? -i : i;
    i = (i >= n) ? (2 * n - 2 - i) : i;
    return i;
}

__device__ __forceinline__ uint64_t bcast2(float f) {
    uint32_t b = __float_as_uint(f);
    return ((uint64_t)b << 32) | (uint64_t)b;
}

__device__ __forceinline__ void ffma2(uint64_t& d, uint64_t a, uint64_t b, uint64_t c) {
    asm("fma.rn.f32x2 %0, %1, %2, %3;" : "=l"(d) : "l"(a), "l"(b), "l"(c));
}

__global__ __launch_bounds__(NTHREADS)
void gauss_blur_fused(const float* __restrict__ in, float* __restrict__ out) {
    __shared__ __align__(16) float s[SIN_H][SIN_W];   // 28224 B, row stride 336B (mult of 16)

    const int tid = threadIdx.x;
    const int x0 = blockIdx.x * TW;
    const int y0 = blockIdx.y * TH;
    const float* __restrict__ base = in + (size_t)blockIdx.z * (IMG_W * IMG_H);

    // ---- Load 84x84 input tile (halo included) ----
    const bool interior = (x0 >= PAD) && (x0 + TW + PAD <= IMG_W) &&
                          (y0 >= PAD) && (y0 + TH + PAD <= IMG_H);
    if (interior) {
        // vectorized float2 path: 3528 LDG.64, 8B-aligned (x0-10 even, stride even)
        int r = tid / 42;          // 42 float2 per row
        int c2 = tid - r * 42;
        const char* g = (const char*)(base + (size_t)(y0 - PAD + r) * IMG_W + (x0 - PAD) + 2 * c2);
        uint64_t* srow = (uint64_t*)&s[0][0];
        int sidx = r * 42 + c2;
        #pragma unroll
        for (int it = 0; it < (NLOAD2 + NTHREADS - 1) / NTHREADS; ++it) {
            if (r < SIN_H) srow[sidx] = __ldg((const uint64_t*)g);
            // advance 512 float2: 512 = 12*42 + 8
            c2 += 8;
            bool wrap = (c2 >= 42);
            c2 = wrap ? (c2 - 42) : c2;
            r += wrap ? 13 : 12;
            g += wrap ? (13 * IMG_W * 4 + (8 - 42) * 8) : (12 * IMG_W * 4 + 8 * 8);
            sidx += NTHREADS;
        }
    } else {
        int r = tid / SIN_W;
        int c = tid - r * SIN_W;
        float* sflat = &s[0][0];
        #pragma unroll
        for (int it = 0; it < (NLOAD + NTHREADS - 1) / NTHREADS; ++it) {
            if (r < SIN_H) {
                int gy = reflect_idx(y0 - PAD + r, IMG_H);
                int gx = reflect_idx(x0 - PAD + c, IMG_W);
                sflat[r * SIN_W + c] = __ldg(base + (size_t)gy * IMG_W + gx);
            }
            c += 8;                      // 512 = 6*84 + 8
            bool wrap = (c >= SIN_W);
            c = wrap ? (c - SIN_W) : c;
            r += wrap ? 7 : 6;
        }
    }
    __syncthreads();

    // ---- Horizontal pass, in place: 84 rows x 4 segments of 16 outputs ----
    {
        const bool hactive = (tid < SIN_H * 4);   // 336 of 512
        const int row = tid >> 2;
        const int seg = (tid & 3) << 4;
        float v[36];
        float o[16];
        if (hactive) {
            const float4* p = reinterpret_cast<const float4*>(&s[row][seg]);
            #pragma unroll
            for (int q = 0; q < 9; ++q) {
                float4 t = p[q];
                v[4 * q + 0] = t.x; v[4 * q + 1] = t.y;
                v[4 * q + 2] = t.z; v[4 * q + 3] = t.w;
            }
            #pragma unroll
            for (int c = 0; c < 16; ++c) {
                float acc = v[c] * tap(0);
                #pragma unroll
                for (int j = 1; j < KS; ++j) acc = fmaf(v[c + j], tap(j), acc);
                o[c] = acc;
            }
        }
        __syncthreads();
        if (hactive) {
            float4* q = reinterpret_cast<float4*>(&s[row][seg]);
            #pragma unroll
            for (int k = 0; k < 4; ++k)
                q[k] = make_float4(o[4 * k], o[4 * k + 1], o[4 * k + 2], o[4 * k + 3]);
        }
    }
    __syncthreads();

    // ---- Vertical pass, packed f32x2: col-pair x 4 rows per thread ----
    // 32 col-pairs x 16 row-groups = 512 threads, 8 outputs each.
    {
        const int cp = tid & 31;          // column pair index: cols 2cp, 2cp+1
        const int g = (tid >> 5) << 2;    // first output row in tile: 0,4,...,60

        uint64_t wp[11];
        #pragma unroll
        for (int j = 0; j <= 10; ++j) wp[j] = bcast2(tap(j));

        uint64_t acc[4] = {0, 0, 0, 0};

        #pragma unroll
        for (int t = 0; t < 24; ++t) {
            uint64_t v2 = *reinterpret_cast<const uint64_t*>(&s[g + t][2 * cp]);
            #pragma unroll
            for (int o = 0; o < 4; ++o) {
                int j = t - o;
                if (j >= 0 && j < KS) {
                    int wi = (j <= 10) ? j : (20 - j);
                    ffma2(acc[o], v2, wp[wi], acc[o]);
                }
            }
        }

        char* dst = (char*)(out + (size_t)blockIdx.z * (IMG_W * IMG_H)
                                + (size_t)(y0 + g) * IMG_W + (x0 + 2 * cp));
        #pragma unroll
        for (int o = 0; o < 4; ++o)
            *reinterpret_cast<uint64_t*>(dst + (size_t)o * IMG_W * 4) = acc[o];
    }
}

extern "C" void kernel_launch(void* const* d_in, const int* in_sizes, int n_in,
                              void* d_out, int out_size) {
    (void)in_sizes; (void)n_in; (void)out_size;
    const float* x = (const float*)d_in[0];
    float* y = (float*)d_out;
    dim3 grid(IMG_W / TW, IMG_H / TH, NIMG);  // 8 x 8 x 96
    gauss_blur_fused<<<grid, NTHREADS>>>(x, y);
}